// round 5
// baseline (speedup 1.0000x reference)
#include <cuda_runtime.h>

#define SEG   3456   // h-elements per warp (multiple of 32); 4855 warps -> 304 blocks = 2/SM on GB300
#define WARM  128    // warm-up elements (beta^128 * h ~ 6e-11 absolute, h ~ 0.067)
#define HEAD  160    // head region recomputed exactly from h0 in the finalize kernel
#define MAXPB 4096   // max partial blocks

__device__ float g_psum[MAXPB];
__device__ float g_psumsq[MAXPB];

// ---------------- Pass 1 (fused): GARCH warp-scan + variance partials ----------------
// Warp w owns h-outputs t in [1 + w*SEG, 1 + (w+1)*SEG), lanes map to consecutive t
// (fully coalesced). Inclusive Kogge-Stone scan with constant ratio beta via shfl;
// only serial dependence is one FMA per 32 elements (H carry). Segment state is
// resynchronized with a WARM-element warm-up from H=0 (beta^WARM negligible) -> no
// inter-warp communication. Each warp also accumulates sum / sum-of-squares over its
// OWNED r-range [w*SEG, (w+1)*SEG) exactly once (warm-up rows excluded; r[n-1]
// unused by the recurrence, folded in at finalize). Outputs t in [1, HEAD] are
// missing the beta^t*h0 term here; the finalize kernel overwrites them exactly.
// All streams are zero-reuse -> streaming cache hints (ldcs/stcs) to keep L2 clean.
__global__ __launch_bounds__(512, 2) void garch_fused_kernel(
    const float* __restrict__ r,
    const float* __restrict__ omega_p, const float* __restrict__ alpha_p,
    const float* __restrict__ beta_p,  const float* __restrict__ gamma_p,
    float* __restrict__ out, int n)
{
    const int tid   = threadIdx.x;
    const int gwarp = (blockIdx.x * blockDim.x + tid) >> 5;
    const int lane  = tid & 31;
    const int start = 1 + gwarp * SEG;
    const int end   = min(n, start + SEG);

    const float omega = *omega_p;
    const float alpha = *alpha_p;
    const float beta  = *beta_p;
    const float gamma = *gamma_p;

    const float b1 = beta;
    const float b2 = b1 * b1, b4 = b2 * b2, b8 = b4 * b4, b16 = b8 * b8, b32 = b16 * b16;

    // bl = beta^(lane+1) by binary composition
    int e = lane + 1;
    float bl = 1.f;
    if (e & 1)  bl *= b1;
    if (e & 2)  bl *= b2;
    if (e & 4)  bl *= b4;
    if (e & 8)  bl *= b8;
    if (e & 16) bl *= b16;
    if (e & 32) bl *= b32;

    float H = 0.f;          // scan carry (resync state)
    float s = 0.f, q = 0.f; // variance partials over owned range

    if (start < n) {
        const int t0 = max(1, start - WARM);

        // ---- warm-up rows: scan only, no writes, no accumulation ----
        for (int tb = t0; tb < start; tb += 32) {
            float rv = __ldcs(r + tb + lane - 1);
            float coef = (rv < 0.f) ? (alpha + gamma) : alpha;
            float v = fmaf(coef * rv, rv, omega);
            float u;
            u = __shfl_up_sync(0xffffffffu, v, 1);  if (lane >= 1)  v = fmaf(b1,  u, v);
            u = __shfl_up_sync(0xffffffffu, v, 2);  if (lane >= 2)  v = fmaf(b2,  u, v);
            u = __shfl_up_sync(0xffffffffu, v, 4);  if (lane >= 4)  v = fmaf(b4,  u, v);
            u = __shfl_up_sync(0xffffffffu, v, 8);  if (lane >= 8)  v = fmaf(b8,  u, v);
            u = __shfl_up_sync(0xffffffffu, v, 16); if (lane >= 16) v = fmaf(b16, u, v);
            H = fmaf(b32, H, __shfl_sync(0xffffffffu, v, 31));
        }

        // ---- main rows, full 32-wide (no bounds predicates) ----
        const int len      = end - start;
        const int full_end = start + (len & ~31);

        #pragma unroll 8
        for (int tb = start; tb < full_end; tb += 32) {
            int t = tb + lane;
            float rv = __ldcs(r + t - 1);
            s += rv; q = fmaf(rv, rv, q);
            float coef = (rv < 0.f) ? (alpha + gamma) : alpha;
            float v = fmaf(coef * rv, rv, omega);
            float u;
            u = __shfl_up_sync(0xffffffffu, v, 1);  if (lane >= 1)  v = fmaf(b1,  u, v);
            u = __shfl_up_sync(0xffffffffu, v, 2);  if (lane >= 2)  v = fmaf(b2,  u, v);
            u = __shfl_up_sync(0xffffffffu, v, 4);  if (lane >= 4)  v = fmaf(b4,  u, v);
            u = __shfl_up_sync(0xffffffffu, v, 8);  if (lane >= 8)  v = fmaf(b8,  u, v);
            u = __shfl_up_sync(0xffffffffu, v, 16); if (lane >= 16) v = fmaf(b16, u, v);

            float h = fmaf(bl, H, v);
            H = fmaf(b32, H, __shfl_sync(0xffffffffu, v, 31));

            float sh;
            asm("sqrt.approx.f32 %0, %1;" : "=f"(sh) : "f"(h));
            __stcs(out + t,     sh);
            __stcs(out + n + t, h);
        }

        // ---- ragged tail row (last warp only) ----
        if (full_end < end) {
            int t = full_end + lane;
            bool ok = (t < end);
            float rv = ok ? __ldcs(r + t - 1) : 0.f;
            if (ok) { s += rv; q = fmaf(rv, rv, q); }
            float coef = (rv < 0.f) ? (alpha + gamma) : alpha;
            float v = ok ? fmaf(coef * rv, rv, omega) : 0.f;
            float u;
            u = __shfl_up_sync(0xffffffffu, v, 1);  if (lane >= 1)  v = fmaf(b1,  u, v);
            u = __shfl_up_sync(0xffffffffu, v, 2);  if (lane >= 2)  v = fmaf(b2,  u, v);
            u = __shfl_up_sync(0xffffffffu, v, 4);  if (lane >= 4)  v = fmaf(b4,  u, v);
            u = __shfl_up_sync(0xffffffffu, v, 8);  if (lane >= 8)  v = fmaf(b8,  u, v);
            u = __shfl_up_sync(0xffffffffu, v, 16); if (lane >= 16) v = fmaf(b16, u, v);
            float h = fmaf(bl, H, v);
            if (ok) {
                float sh;
                asm("sqrt.approx.f32 %0, %1;" : "=f"(sh) : "f"(h));
                __stcs(out + t,     sh);
                __stcs(out + n + t, h);
            }
        }
    }

    // ---- block-level reduction of variance partials (all threads participate) ----
    for (int d = 16; d; d >>= 1) {
        s += __shfl_down_sync(0xffffffffu, s, d);
        q += __shfl_down_sync(0xffffffffu, q, d);
    }
    __shared__ float ss[16], sq[16];
    if (lane == 0) { ss[tid >> 5] = s; sq[tid >> 5] = q; }
    __syncthreads();
    if (tid < 16) {
        s = ss[tid]; q = sq[tid];
        for (int d = 8; d; d >>= 1) {
            s += __shfl_down_sync(0xffffu, s, d);
            q += __shfl_down_sync(0xffffu, q, d);
        }
        if (tid == 0) { g_psum[blockIdx.x] = s; g_psumsq[blockIdx.x] = q; }
    }
}

// ---------------- Pass 2: finalize variance + exact head recompute ----------------
__global__ __launch_bounds__(512) void finalize_kernel(
    const float* __restrict__ r,
    const float* __restrict__ omega_p, const float* __restrict__ alpha_p,
    const float* __restrict__ beta_p,  const float* __restrict__ gamma_p,
    float* __restrict__ out, int n, int pb)
{
    const int tid  = threadIdx.x;
    const int lane = tid & 31;

    float s = 0.f, q = 0.f;
    for (int i = tid; i < pb; i += 512) { s += g_psum[i]; q += g_psumsq[i]; }
    for (int d = 16; d; d >>= 1) {
        s += __shfl_down_sync(0xffffffffu, s, d);
        q += __shfl_down_sync(0xffffffffu, q, d);
    }
    __shared__ float ss[16], sq[16];
    __shared__ float sh_var;
    if (lane == 0) { ss[tid >> 5] = s; sq[tid >> 5] = q; }
    __syncthreads();
    if (tid < 16) {
        s = ss[tid]; q = sq[tid];
        for (int d = 8; d; d >>= 1) {
            s += __shfl_down_sync(0xffffu, s, d);
            q += __shfl_down_sync(0xffffu, q, d);
        }
        if (tid == 0) {
            // fold in r[n-1] (unused by the recurrence, excluded from partials)
            float v = r[n - 1];
            s += v; q = fmaf(v, v, q);
            float inv = 1.f / (float)n;
            float var = fmaf(-(s * inv), s, q) / (float)(n - 1);  // (q - s^2/n)/(n-1)
            sh_var = var;
            out[0] = sqrtf(var);
            out[n] = var;
        }
    }
    __syncthreads();

    // ---- exact head: recompute t in [1, HEAD] from h0 and overwrite ----
    if (tid < 32) {
        const float omega = *omega_p;
        const float alpha = *alpha_p;
        const float beta  = *beta_p;
        const float gamma = *gamma_p;
        const float b1 = beta;
        const float b2 = b1 * b1, b4 = b2 * b2, b8 = b4 * b4, b16 = b8 * b8, b32 = b16 * b16;
        int e = lane + 1;
        float bl = 1.f;
        if (e & 1)  bl *= b1;
        if (e & 2)  bl *= b2;
        if (e & 4)  bl *= b4;
        if (e & 8)  bl *= b8;
        if (e & 16) bl *= b16;
        if (e & 32) bl *= b32;

        float H = sh_var;
        int head_end = min(n, HEAD + 1);
        for (int tb = 1; tb < head_end; tb += 32) {
            int t = tb + lane;
            bool ok = (t < head_end);
            float rv = ok ? r[t - 1] : 0.f;
            float coef = (rv < 0.f) ? (alpha + gamma) : alpha;
            float v = ok ? fmaf(coef * rv, rv, omega) : 0.f;
            float u;
            u = __shfl_up_sync(0xffffffffu, v, 1);  if (lane >= 1)  v = fmaf(b1,  u, v);
            u = __shfl_up_sync(0xffffffffu, v, 2);  if (lane >= 2)  v = fmaf(b2,  u, v);
            u = __shfl_up_sync(0xffffffffu, v, 4);  if (lane >= 4)  v = fmaf(b4,  u, v);
            u = __shfl_up_sync(0xffffffffu, v, 8);  if (lane >= 8)  v = fmaf(b8,  u, v);
            u = __shfl_up_sync(0xffffffffu, v, 16); if (lane >= 16) v = fmaf(b16, u, v);
            float h = fmaf(bl, H, v);
            H = fmaf(b32, H, __shfl_sync(0xffffffffu, v, 31));
            if (ok) {
                out[t]     = sqrtf(h);
                out[n + t] = h;
            }
        }
    }
}

extern "C" void kernel_launch(void* const* d_in, const int* in_sizes, int n_in,
                              void* d_out, int out_size) {
    const float* returns = (const float*)d_in[0];
    const float* omega_p = (const float*)d_in[1];
    const float* alpha_p = (const float*)d_in[2];
    const float* beta_p  = (const float*)d_in[3];
    const float* gamma_p = (const float*)d_in[4];
    float* out = (float*)d_out;
    int n = in_sizes[0];

    int nwarps = (n - 1 + SEG - 1) / SEG;            // n=16.7M -> 4855 warps
    if (nwarps < 1) nwarps = 1;
    int blocks = (nwarps + 15) / 16;                 // 512-thr blocks -> 304 = 2/SM on 152 SMs
    if (blocks > MAXPB) blocks = MAXPB;

    garch_fused_kernel<<<blocks, 512>>>(returns, omega_p, alpha_p, beta_p, gamma_p, out, n);
    finalize_kernel<<<1, 512>>>(returns, omega_p, alpha_p, beta_p, gamma_p, out, n, blocks);
}

// round 11
// speedup vs baseline: 1.8541x; 1.8541x over previous
#include <cuda_runtime.h>

#define SEGV  3456   // outputs per warp = 27 rows of 128
#define HEAD  160    // head region recomputed exactly from h0 by the last block
#define MAXPB 8192

__device__ float g_psum[MAXPB];
__device__ float g_psumsq[MAXPB];
__device__ unsigned int g_done = 0;

// Fused GJR-GARCH: vectorized warp-scan recurrence + variance partials + last-block
// finalize. Each warp owns outputs t in [A, A+SEGV), 4 consecutive t per lane
// (float4 loads/stores, fully coalesced). Inclusive scan: per-lane 4-elem serial
// prefix, then 5-stage Kogge-Stone across lanes with ratio beta^4. Only serial
// dependence across rows: H = fma(beta^128, H, v31). Segments resync via one
// 128-elem warm-up row from H=0 (beta^128 ~ 1e-9 relative). Outputs t in [0,HEAD]
// lack the beta^t*h0 term; the last block overwrites them exactly after computing
// h0 = var(returns) from the per-block partials (threadfence+atomic ordering).
__global__ __launch_bounds__(256, 4) void garch_kernel(
    const float* __restrict__ r,
    const float* __restrict__ omega_p, const float* __restrict__ alpha_p,
    const float* __restrict__ beta_p,  const float* __restrict__ gamma_p,
    float* __restrict__ out, int n)
{
    __shared__ float ss[8], sq[8];
    __shared__ float sh_var;
    __shared__ unsigned int sh_last;

    const int tid   = threadIdx.x;
    const int lane  = tid & 31;
    const int gwarp = (blockIdx.x * blockDim.x + tid) >> 5;
    const int A     = gwarp * SEGV;
    const int end   = min(n, A + SEGV);

    const float omega = *omega_p;
    const float alpha = *alpha_p;
    const float beta  = *beta_p;
    const float gamma = *gamma_p;
    const float ag    = alpha + gamma;

    const float b1 = beta, b2 = b1 * b1, b3 = b2 * b1, b4 = b2 * b2, b8 = b4 * b4,
                b16 = b8 * b8, b32 = b16 * b16, b64 = b32 * b32, b128 = b64 * b64;
    // b4l = beta^(4*lane)
    float b4l = 1.f;
    if (lane & 1)  b4l *= b4;
    if (lane & 2)  b4l *= b8;
    if (lane & 4)  b4l *= b16;
    if (lane & 8)  b4l *= b32;
    if (lane & 16) b4l *= b64;
    // blsc = beta^(lane+1) (scalar-tail / head paths)
    float blsc = 1.f;
    {
        int e2 = lane + 1;
        if (e2 & 1)  blsc *= b1;
        if (e2 & 2)  blsc *= b2;
        if (e2 & 4)  blsc *= b4;
        if (e2 & 8)  blsc *= b8;
        if (e2 & 16) blsc *= b16;
        if (e2 & 32) blsc *= b32;
    }

    float H = 0.f, prevtail = 0.f;
    float s = 0.f, q = 0.f;

// One row = 128 outputs t in [TB, TB+128). Lane l: outputs t = TB+4l+j (j=0..3),
// needing r[t-1] = {prev lane's R.w, R.x, R.y, R.z}. DO_OUT=false -> warm-up
// (state only, no stores, no variance accumulation).
#define GARCH_ROW(TB, DO_OUT)                                                       \
    {                                                                               \
        float4 R = __ldcs((const float4*)(r + (TB) + (lane << 2)));                 \
        float r0 = __shfl_up_sync(0xffffffffu, R.w, 1);                             \
        if (lane == 0) r0 = prevtail;                                               \
        prevtail = __shfl_sync(0xffffffffu, R.w, 31);                               \
        float c0 = fmaf(((r0  < 0.f) ? ag : alpha) * r0,  r0,  omega);              \
        float c1 = fmaf(((R.x < 0.f) ? ag : alpha) * R.x, R.x, omega);              \
        float c2 = fmaf(((R.y < 0.f) ? ag : alpha) * R.y, R.y, omega);              \
        float c3 = fmaf(((R.z < 0.f) ? ag : alpha) * R.z, R.z, omega);              \
        float p1 = fmaf(b1, c0, c1);                                                \
        float p2 = fmaf(b1, p1, c2);                                                \
        float p3 = fmaf(b1, p2, c3);                                                \
        float v = p3, u;                                                            \
        u = __shfl_up_sync(0xffffffffu, v, 1);  if (lane >= 1)  v = fmaf(b4,  u, v); \
        u = __shfl_up_sync(0xffffffffu, v, 2);  if (lane >= 2)  v = fmaf(b8,  u, v); \
        u = __shfl_up_sync(0xffffffffu, v, 4);  if (lane >= 4)  v = fmaf(b16, u, v); \
        u = __shfl_up_sync(0xffffffffu, v, 8);  if (lane >= 8)  v = fmaf(b32, u, v); \
        u = __shfl_up_sync(0xffffffffu, v, 16); if (lane >= 16) v = fmaf(b64, u, v); \
        float X = __shfl_up_sync(0xffffffffu, v, 1);                                \
        if (lane == 0) X = 0.f;                                                     \
        float S = fmaf(b4l, H, X);              /* h at t = TB+4*lane-1 */          \
        H = fmaf(b128, H, __shfl_sync(0xffffffffu, v, 31));                         \
        if (DO_OUT) {                                                               \
            s += (R.x + R.y) + (R.z + R.w);                                         \
            q = fmaf(R.x, R.x, q); q = fmaf(R.y, R.y, q);                           \
            q = fmaf(R.z, R.z, q); q = fmaf(R.w, R.w, q);                           \
            float h0 = fmaf(b1, S, c0);                                             \
            float h1 = fmaf(b2, S, p1);                                             \
            float h2 = fmaf(b3, S, p2);                                             \
            float h3 = fmaf(b4, S, p3);                                             \
            float s0, s1, s2, s3;                                                   \
            asm("sqrt.approx.f32 %0, %1;" : "=f"(s0) : "f"(h0));                    \
            asm("sqrt.approx.f32 %0, %1;" : "=f"(s1) : "f"(h1));                    \
            asm("sqrt.approx.f32 %0, %1;" : "=f"(s2) : "f"(h2));                    \
            asm("sqrt.approx.f32 %0, %1;" : "=f"(s3) : "f"(h3));                    \
            int o = (TB) + (lane << 2);                                             \
            __stcs((float4*)(out + o),     make_float4(s0, s1, s2, s3));            \
            __stcs((float4*)(out + n + o), make_float4(h0, h1, h2, h3));            \
        }                                                                           \
    }

    if (A < n) {
        const int rows = (end - A) >> 7;

        if (A > 0) {
            if (lane == 0) prevtail = __ldg(r + A - 129);
            GARCH_ROW(A - 128, false)          // warm-up row (state only)
        }
        // else: prevtail=0 -> t=0 output is garbage; overwritten by finalize/head.

        int tb = A;
        #pragma unroll 4
        for (int i = 0; i < rows; ++i, tb += 128) {
            GARCH_ROW(tb, true)
        }

        // generic ragged tail (<128 remainder; not taken for n = 2^24)
        for (; tb < end; tb += 32) {
            int t = tb + lane;
            bool ok = (t < end);
            float rp = (ok && t >= 1) ? r[t - 1] : 0.f;
            float rc = ok ? r[t] : 0.f;
            if (ok) { s += rc; q = fmaf(rc, rc, q); }
            float c = ok ? fmaf(((rp < 0.f) ? ag : alpha) * rp, rp, omega) : 0.f;
            float v = c, u;
            u = __shfl_up_sync(0xffffffffu, v, 1);  if (lane >= 1)  v = fmaf(b1,  u, v);
            u = __shfl_up_sync(0xffffffffu, v, 2);  if (lane >= 2)  v = fmaf(b2,  u, v);
            u = __shfl_up_sync(0xffffffffu, v, 4);  if (lane >= 4)  v = fmaf(b4,  u, v);
            u = __shfl_up_sync(0xffffffffu, v, 8);  if (lane >= 8)  v = fmaf(b8,  u, v);
            u = __shfl_up_sync(0xffffffffu, v, 16); if (lane >= 16) v = fmaf(b16, u, v);
            float h = fmaf(blsc, H, v);
            H = fmaf(b32, H, __shfl_sync(0xffffffffu, v, 31));
            if (ok && t >= 1) {
                out[t]     = sqrtf(h);
                out[n + t] = h;
            }
        }
    }

    // ---- block reduction of variance partials ----
    for (int d = 16; d; d >>= 1) {
        s += __shfl_down_sync(0xffffffffu, s, d);
        q += __shfl_down_sync(0xffffffffu, q, d);
    }
    if (lane == 0) { ss[tid >> 5] = s; sq[tid >> 5] = q; }
    __syncthreads();
    if (tid < 8) {
        s = ss[tid]; q = sq[tid];
        for (int d = 4; d; d >>= 1) {
            s += __shfl_down_sync(0xffu, s, d);
            q += __shfl_down_sync(0xffu, q, d);
        }
        if (tid == 0) { g_psum[blockIdx.x] = s; g_psumsq[blockIdx.x] = q; }
    }

    // ---- last block finalizes (threadfence + atomic ordering) ----
    __threadfence();
    if (tid == 0) {
        unsigned int prev = atomicAdd(&g_done, 1u);
        sh_last = (prev == gridDim.x - 1) ? 1u : 0u;
    }
    __syncthreads();
    if (sh_last) {
        float fs = 0.f, fq = 0.f;
        for (int i = tid; i < (int)gridDim.x; i += blockDim.x) {
            fs += g_psum[i]; fq += g_psumsq[i];
        }
        for (int d = 16; d; d >>= 1) {
            fs += __shfl_down_sync(0xffffffffu, fs, d);
            fq += __shfl_down_sync(0xffffffffu, fq, d);
        }
        if (lane == 0) { ss[tid >> 5] = fs; sq[tid >> 5] = fq; }
        __syncthreads();
        if (tid == 0) {
            fs = 0.f; fq = 0.f;
            for (int w = 0; w < 8; ++w) { fs += ss[w]; fq += sq[w]; }
            float inv = 1.f / (float)n;
            float var = fmaf(-(fs * inv), fs, fq) / (float)(n - 1);  // (q - s^2/n)/(n-1)
            sh_var = var;
            out[0] = sqrtf(var);
            out[n] = var;
            g_done = 0;                    // reset for next graph replay
        }
        __syncthreads();

        // exact head: recompute t in [1, HEAD] from h0 and overwrite
        if (tid < 32) {
            float Hh = sh_var;
            int head_end = min(n, HEAD + 1);
            for (int t0 = 1; t0 < head_end; t0 += 32) {
                int t = t0 + lane;
                bool ok = (t < head_end);
                float rp = ok ? r[t - 1] : 0.f;
                float c = ok ? fmaf(((rp < 0.f) ? ag : alpha) * rp, rp, omega) : 0.f;
                float v = c, u;
                u = __shfl_up_sync(0xffffffffu, v, 1);  if (lane >= 1)  v = fmaf(b1,  u, v);
                u = __shfl_up_sync(0xffffffffu, v, 2);  if (lane >= 2)  v = fmaf(b2,  u, v);
                u = __shfl_up_sync(0xffffffffu, v, 4);  if (lane >= 4)  v = fmaf(b4,  u, v);
                u = __shfl_up_sync(0xffffffffu, v, 8);  if (lane >= 8)  v = fmaf(b8,  u, v);
                u = __shfl_up_sync(0xffffffffu, v, 16); if (lane >= 16) v = fmaf(b16, u, v);
                float h = fmaf(blsc, Hh, v);
                Hh = fmaf(b32, Hh, __shfl_sync(0xffffffffu, v, 31));
                if (ok) {
                    out[t]     = sqrtf(h);
                    out[n + t] = h;
                }
            }
        }
    }
#undef GARCH_ROW
}

extern "C" void kernel_launch(void* const* d_in, const int* in_sizes, int n_in,
                              void* d_out, int out_size) {
    const float* returns = (const float*)d_in[0];
    const float* omega_p = (const float*)d_in[1];
    const float* alpha_p = (const float*)d_in[2];
    const float* beta_p  = (const float*)d_in[3];
    const float* gamma_p = (const float*)d_in[4];
    float* out = (float*)d_out;
    int n = in_sizes[0];

    int nwarps = (n + SEGV - 1) / SEGV;       // n=2^24 -> 4855 warps
    if (nwarps < 1) nwarps = 1;
    int blocks = (nwarps + 7) / 8;            // 256-thr blocks -> 607 ~= 4/SM on 152 SMs
    if (blocks > MAXPB) blocks = MAXPB;

    garch_kernel<<<blocks, 256>>>(returns, omega_p, alpha_p, beta_p, gamma_p, out, n);
}

// round 12
// speedup vs baseline: 2.0694x; 1.1161x over previous
#include <cuda_runtime.h>

#define SEGV  4608   // outputs per warp = 18 rows of 256
#define HEAD  160    // head region recomputed exactly from h0 by the last block
#define MAXPB 8192

__device__ float g_psum[MAXPB];
__device__ float g_psumsq[MAXPB];
__device__ unsigned int g_done = 0;

// Fused GJR-GARCH, 8 outputs/lane. Each warp owns t in [A, A+SEGV), 8 consecutive
// t per lane (2x float4 loads, 2x float4 stores per array, fully coalesced).
// Inclusive scan: per-lane 7-FMA serial prefix, then 5-stage Kogge-Stone across
// lanes with ratio beta^8. Serial dependence across rows: H = fma(beta^256, H, v31).
// Segments resync via one 256-elem warm-up row from H=0 (beta^256 negligible).
// Outputs t in [0,HEAD] lack the beta^t*h0 term; the last block overwrites them
// exactly after computing h0 = var(returns) (threadfence+atomic ordering).
__global__ __launch_bounds__(256, 3) void garch_kernel(
    const float* __restrict__ r,
    const float* __restrict__ omega_p, const float* __restrict__ alpha_p,
    const float* __restrict__ beta_p,  const float* __restrict__ gamma_p,
    float* __restrict__ out, int n)
{
    __shared__ float ss[8], sq[8];
    __shared__ float sh_var;
    __shared__ unsigned int sh_last;

    const int tid   = threadIdx.x;
    const int lane  = tid & 31;
    const int gwarp = (blockIdx.x * blockDim.x + tid) >> 5;
    const int A     = gwarp * SEGV;
    const int end   = min(n, A + SEGV);

    const float omega = *omega_p;
    const float alpha = *alpha_p;
    const float beta  = *beta_p;
    const float gamma = *gamma_p;
    const float ag    = alpha + gamma;

    const float b1 = beta, b2 = b1 * b1, b3 = b2 * b1, b4 = b2 * b2,
                b5 = b4 * b1, b6 = b4 * b2, b7 = b4 * b3, b8 = b4 * b4,
                b16 = b8 * b8, b32 = b16 * b16, b64 = b32 * b32,
                b128 = b64 * b64, b256 = b128 * b128;

    // b8l = beta^(8*lane)
    float b8l = 1.f;
    if (lane & 1)  b8l *= b8;
    if (lane & 2)  b8l *= b16;
    if (lane & 4)  b8l *= b32;
    if (lane & 8)  b8l *= b64;
    if (lane & 16) b8l *= b128;
    // blsc = beta^(lane+1) (scalar tail / head paths)
    float blsc = 1.f;
    {
        int e2 = lane + 1;
        if (e2 & 1)  blsc *= b1;
        if (e2 & 2)  blsc *= b2;
        if (e2 & 4)  blsc *= b4;
        if (e2 & 8)  blsc *= b8;
        if (e2 & 16) blsc *= b16;
        if (e2 & 32) blsc *= b32;
    }

    float H = 0.f, prevtail = 0.f;
    float s = 0.f, q = 0.f;

// One row = 256 outputs t in [TB, TB+256). Lane l owns t = TB+8l+j (j=0..7);
// r[t-1] = {prev lane's R2.w, R1.x, R1.y, R1.z, R1.w, R2.x, R2.y, R2.z}.
#define GARCH_ROW8(TB, DO_OUT)                                                       \
    {                                                                                \
        const float* _b = r + (TB) + (lane << 3);                                    \
        float4 R1 = __ldcs((const float4*)_b);                                       \
        float4 R2 = __ldcs((const float4*)(_b + 4));                                 \
        float r0 = __shfl_up_sync(0xffffffffu, R2.w, 1);                             \
        if (lane == 0) r0 = prevtail;                                                \
        prevtail = __shfl_sync(0xffffffffu, R2.w, 31);                               \
        float c0 = fmaf(((r0   < 0.f) ? ag : alpha) * r0,   r0,   omega);            \
        float c1 = fmaf(((R1.x < 0.f) ? ag : alpha) * R1.x, R1.x, omega);            \
        float c2 = fmaf(((R1.y < 0.f) ? ag : alpha) * R1.y, R1.y, omega);            \
        float c3 = fmaf(((R1.z < 0.f) ? ag : alpha) * R1.z, R1.z, omega);            \
        float c4 = fmaf(((R1.w < 0.f) ? ag : alpha) * R1.w, R1.w, omega);            \
        float c5 = fmaf(((R2.x < 0.f) ? ag : alpha) * R2.x, R2.x, omega);            \
        float c6 = fmaf(((R2.y < 0.f) ? ag : alpha) * R2.y, R2.y, omega);            \
        float c7 = fmaf(((R2.z < 0.f) ? ag : alpha) * R2.z, R2.z, omega);            \
        float p1 = fmaf(b1, c0, c1);                                                 \
        float p2 = fmaf(b1, p1, c2);                                                 \
        float p3 = fmaf(b1, p2, c3);                                                 \
        float p4 = fmaf(b1, p3, c4);                                                 \
        float p5 = fmaf(b1, p4, c5);                                                 \
        float p6 = fmaf(b1, p5, c6);                                                 \
        float p7 = fmaf(b1, p6, c7);                                                 \
        float v = p7, u;                                                             \
        u = __shfl_up_sync(0xffffffffu, v, 1);  if (lane >= 1)  v = fmaf(b8,   u, v); \
        u = __shfl_up_sync(0xffffffffu, v, 2);  if (lane >= 2)  v = fmaf(b16,  u, v); \
        u = __shfl_up_sync(0xffffffffu, v, 4);  if (lane >= 4)  v = fmaf(b32,  u, v); \
        u = __shfl_up_sync(0xffffffffu, v, 8);  if (lane >= 8)  v = fmaf(b64,  u, v); \
        u = __shfl_up_sync(0xffffffffu, v, 16); if (lane >= 16) v = fmaf(b128, u, v); \
        float X = __shfl_up_sync(0xffffffffu, v, 1);                                 \
        if (lane == 0) X = 0.f;                                                      \
        float S = fmaf(b8l, H, X);              /* h at t = TB+8*lane-1 */           \
        H = fmaf(b256, H, __shfl_sync(0xffffffffu, v, 31));                          \
        if (DO_OUT) {                                                                \
            s += ((R1.x + R1.y) + (R1.z + R1.w)) + ((R2.x + R2.y) + (R2.z + R2.w));  \
            q = fmaf(R1.x, R1.x, q); q = fmaf(R1.y, R1.y, q);                        \
            q = fmaf(R1.z, R1.z, q); q = fmaf(R1.w, R1.w, q);                        \
            q = fmaf(R2.x, R2.x, q); q = fmaf(R2.y, R2.y, q);                        \
            q = fmaf(R2.z, R2.z, q); q = fmaf(R2.w, R2.w, q);                        \
            float h0 = fmaf(b1, S, c0);                                              \
            float h1 = fmaf(b2, S, p1);                                              \
            float h2 = fmaf(b3, S, p2);                                              \
            float h3 = fmaf(b4, S, p3);                                              \
            float h4 = fmaf(b5, S, p4);                                              \
            float h5 = fmaf(b6, S, p5);                                              \
            float h6 = fmaf(b7, S, p6);                                              \
            float h7 = fmaf(b8, S, p7);                                              \
            float s0, s1, s2, s3, s4, s5, s6, s7;                                    \
            asm("sqrt.approx.f32 %0, %1;" : "=f"(s0) : "f"(h0));                     \
            asm("sqrt.approx.f32 %0, %1;" : "=f"(s1) : "f"(h1));                     \
            asm("sqrt.approx.f32 %0, %1;" : "=f"(s2) : "f"(h2));                     \
            asm("sqrt.approx.f32 %0, %1;" : "=f"(s3) : "f"(h3));                     \
            asm("sqrt.approx.f32 %0, %1;" : "=f"(s4) : "f"(h4));                     \
            asm("sqrt.approx.f32 %0, %1;" : "=f"(s5) : "f"(h5));                     \
            asm("sqrt.approx.f32 %0, %1;" : "=f"(s6) : "f"(h6));                     \
            asm("sqrt.approx.f32 %0, %1;" : "=f"(s7) : "f"(h7));                     \
            int o = (TB) + (lane << 3);                                              \
            __stcs((float4*)(out + o),         make_float4(s0, s1, s2, s3));         \
            __stcs((float4*)(out + o + 4),     make_float4(s4, s5, s6, s7));         \
            __stcs((float4*)(out + n + o),     make_float4(h0, h1, h2, h3));         \
            __stcs((float4*)(out + n + o + 4), make_float4(h4, h5, h6, h7));         \
        }                                                                            \
    }

    if (A < n) {
        const int rows = (end - A) >> 8;

        if (A > 0) {
            if (lane == 0) prevtail = __ldg(r + A - 257);
            GARCH_ROW8(A - 256, false)         // warm-up row (state only)
        }
        // else: prevtail=0 -> t=0 output is garbage; overwritten by finalize/head.

        int tb = A;
        #pragma unroll 2
        for (int i = 0; i < rows; ++i, tb += 256) {
            GARCH_ROW8(tb, true)
        }

        // generic ragged tail (<256 remainder; not taken for n = 2^24)
        for (; tb < end; tb += 32) {
            int t = tb + lane;
            bool ok = (t < end);
            float rp = (ok && t >= 1) ? r[t - 1] : 0.f;
            float rc = ok ? r[t] : 0.f;
            if (ok) { s += rc; q = fmaf(rc, rc, q); }
            float c = ok ? fmaf(((rp < 0.f) ? ag : alpha) * rp, rp, omega) : 0.f;
            float v = c, u;
            u = __shfl_up_sync(0xffffffffu, v, 1);  if (lane >= 1)  v = fmaf(b1,  u, v);
            u = __shfl_up_sync(0xffffffffu, v, 2);  if (lane >= 2)  v = fmaf(b2,  u, v);
            u = __shfl_up_sync(0xffffffffu, v, 4);  if (lane >= 4)  v = fmaf(b4,  u, v);
            u = __shfl_up_sync(0xffffffffu, v, 8);  if (lane >= 8)  v = fmaf(b8,  u, v);
            u = __shfl_up_sync(0xffffffffu, v, 16); if (lane >= 16) v = fmaf(b16, u, v);
            float h = fmaf(blsc, H, v);
            H = fmaf(b32, H, __shfl_sync(0xffffffffu, v, 31));
            if (ok && t >= 1) {
                out[t]     = sqrtf(h);
                out[n + t] = h;
            }
        }
    }

    // ---- block reduction of variance partials ----
    for (int d = 16; d; d >>= 1) {
        s += __shfl_down_sync(0xffffffffu, s, d);
        q += __shfl_down_sync(0xffffffffu, q, d);
    }
    if (lane == 0) { ss[tid >> 5] = s; sq[tid >> 5] = q; }
    __syncthreads();
    if (tid < 8) {
        s = ss[tid]; q = sq[tid];
        for (int d = 4; d; d >>= 1) {
            s += __shfl_down_sync(0xffu, s, d);
            q += __shfl_down_sync(0xffu, q, d);
        }
        if (tid == 0) { g_psum[blockIdx.x] = s; g_psumsq[blockIdx.x] = q; }
    }

    // ---- last block finalizes (threadfence + atomic ordering) ----
    __threadfence();
    if (tid == 0) {
        unsigned int prev = atomicAdd(&g_done, 1u);
        sh_last = (prev == gridDim.x - 1) ? 1u : 0u;
    }
    __syncthreads();
    if (sh_last) {
        float fs = 0.f, fq = 0.f;
        for (int i = tid; i < (int)gridDim.x; i += blockDim.x) {
            fs += g_psum[i]; fq += g_psumsq[i];
        }
        for (int d = 16; d; d >>= 1) {
            fs += __shfl_down_sync(0xffffffffu, fs, d);
            fq += __shfl_down_sync(0xffffffffu, fq, d);
        }
        if (lane == 0) { ss[tid >> 5] = fs; sq[tid >> 5] = fq; }
        __syncthreads();
        if (tid == 0) {
            fs = 0.f; fq = 0.f;
            for (int w = 0; w < 8; ++w) { fs += ss[w]; fq += sq[w]; }
            float inv = 1.f / (float)n;
            float var = fmaf(-(fs * inv), fs, fq) / (float)(n - 1);  // (q - s^2/n)/(n-1)
            sh_var = var;
            out[0] = sqrtf(var);
            out[n] = var;
            g_done = 0;                    // reset for next graph replay
        }
        __syncthreads();

        // exact head: recompute t in [1, HEAD] from h0 and overwrite
        if (tid < 32) {
            float Hh = sh_var;
            int head_end = min(n, HEAD + 1);
            for (int t0 = 1; t0 < head_end; t0 += 32) {
                int t = t0 + lane;
                bool ok = (t < head_end);
                float rp = ok ? r[t - 1] : 0.f;
                float c = ok ? fmaf(((rp < 0.f) ? ag : alpha) * rp, rp, omega) : 0.f;
                float v = c, u;
                u = __shfl_up_sync(0xffffffffu, v, 1);  if (lane >= 1)  v = fmaf(b1,  u, v);
                u = __shfl_up_sync(0xffffffffu, v, 2);  if (lane >= 2)  v = fmaf(b2,  u, v);
                u = __shfl_up_sync(0xffffffffu, v, 4);  if (lane >= 4)  v = fmaf(b4,  u, v);
                u = __shfl_up_sync(0xffffffffu, v, 8);  if (lane >= 8)  v = fmaf(b8,  u, v);
                u = __shfl_up_sync(0xffffffffu, v, 16); if (lane >= 16) v = fmaf(b16, u, v);
                float h = fmaf(blsc, Hh, v);
                Hh = fmaf(b32, Hh, __shfl_sync(0xffffffffu, v, 31));
                if (ok) {
                    out[t]     = sqrtf(h);
                    out[n + t] = h;
                }
            }
        }
    }
#undef GARCH_ROW8
}

extern "C" void kernel_launch(void* const* d_in, const int* in_sizes, int n_in,
                              void* d_out, int out_size) {
    const float* returns = (const float*)d_in[0];
    const float* omega_p = (const float*)d_in[1];
    const float* alpha_p = (const float*)d_in[2];
    const float* beta_p  = (const float*)d_in[3];
    const float* gamma_p = (const float*)d_in[4];
    float* out = (float*)d_out;
    int n = in_sizes[0];

    int nwarps = (n + SEGV - 1) / SEGV;       // n=2^24 -> 3641 warps
    if (nwarps < 1) nwarps = 1;
    int blocks = (nwarps + 7) / 8;            // 256-thr blocks -> 456 = 3/SM on 152 SMs
    if (blocks > MAXPB) blocks = MAXPB;

    garch_kernel<<<blocks, 256>>>(returns, omega_p, alpha_p, beta_p, gamma_p, out, n);
}